// round 4
// baseline (speedup 1.0000x reference)
#include <cuda_runtime.h>
#include <math_constants.h>

// Problem constants (fixed by setup_inputs): B=8, N=128, H=256, F=1023
#define B_ 8
#define N_ 128
#define H_ 256

#define BM 32
#define BN 32
#define BK 64
#define ASTR 68   // A-tile row stride (floats): 16B-aligned float4 stores
#define BSTR 65   // B-tile row stride (floats): conflict-free b-reads

// Scratch: per-(row, j-tile) partial argmax + completion counter
__device__ float g_pval[B_ * N_ * 4];
__device__ int   g_pidx[B_ * N_ * 4];
__device__ int   g_cnt;          // zero-initialized; last block resets to 0

// ---------------------------------------------------------------------------
// Fused kernel: per block one 32x32 tile of logits[b].
//   prologue: r_i = x_i.W0 + bias, s_j = x_j.W1  (smem)
//   main:     C = Xi @ (Xj*W2)^T over K=256
//   epilogue: logits = C + r_i + s_j + W3[j+127-a(b,i)], mask, store,
//             partial argmax -> scratch; last-arriving block decodes preds.
// ---------------------------------------------------------------------------
__global__ void __launch_bounds__(128)
pair_fused_kernel(const float* __restrict__ x,
                  const int* __restrict__ mask,
                  const float* __restrict__ W,
                  const float* __restrict__ bias,
                  float* __restrict__ out,
                  float* __restrict__ preds) {
    __shared__ float As[BM * ASTR];
    __shared__ float Bs[BN * BSTR];
    __shared__ float rs[64];              // [0:32) r_i(+bias), [32:64) s_j

    const int t  = threadIdx.x;
    const int jt = blockIdx.x, it = blockIdx.y, bb = blockIdx.z;
    const int i0 = it * BM, j0 = jt * BN;
    const float* xb = x + bb * N_ * H_;
    const float* W2 = W + 2 * H_;

    // ---- prologue: row dots ------------------------------------------------
    {
        const int pr   = t >> 1;          // 0..63
        const int half = t & 1;           // k-half
        const int grow = (pr < 32) ? (i0 + pr) : (j0 + (pr - 32));
        const float* xr = xb + grow * H_ + half * 128;
        const float* wr = W + ((pr < 32) ? 0 : H_) + half * 128;
        float sum = 0.f;
#pragma unroll
        for (int q = 0; q < 32; q++) {
            float4 xv = ((const float4*)xr)[q];
            float4 wv = ((const float4*)wr)[q];
            sum += xv.x * wv.x + xv.y * wv.y + xv.z * wv.z + xv.w * wv.w;
        }
        sum += __shfl_xor_sync(0xffffffffu, sum, 1);
        if (half == 0) rs[pr] = sum + ((pr < 32) ? bias[0] : 0.f);
    }

    // ---- main GEMM ---------------------------------------------------------
    const int lr = t >> 4;   // loader row group 0..7
    const int lc = t & 15;   // loader k-quad 0..15
    const int ig = t >> 4;   // compute: 8 groups of 4 rows
    const int jg = t & 15;   // compute: 16 groups of 2 cols

    float acc[4][2] = {};

    for (int k0 = 0; k0 < H_; k0 += BK) {
        __syncthreads();     // covers prologue on first iter, reads on later
        float4 wv = *(const float4*)(W2 + k0 + lc * 4);
#pragma unroll
        for (int rep = 0; rep < 4; rep++) {
            int row = lr + rep * 8;
            float4 av = *(const float4*)(xb + (i0 + row) * H_ + k0 + lc * 4);
            float4 bv = *(const float4*)(xb + (j0 + row) * H_ + k0 + lc * 4);
            *(float4*)(As + row * ASTR + lc * 4) = av;
            Bs[row * BSTR + lc * 4 + 0] = bv.x * wv.x;
            Bs[row * BSTR + lc * 4 + 1] = bv.y * wv.y;
            Bs[row * BSTR + lc * 4 + 2] = bv.z * wv.z;
            Bs[row * BSTR + lc * 4 + 3] = bv.w * wv.w;
        }
        __syncthreads();

        const float* ap = As + (ig * 4) * ASTR;
        const float* bp = Bs + (jg * 2) * BSTR;
#pragma unroll
        for (int k = 0; k < BK; k++) {
            float a0 = ap[0 * ASTR + k];
            float a1 = ap[1 * ASTR + k];
            float a2 = ap[2 * ASTR + k];
            float a3 = ap[3 * ASTR + k];
            float b0 = bp[0 * BSTR + k];
            float b1 = bp[1 * BSTR + k];
            acc[0][0] += a0 * b0; acc[0][1] += a0 * b1;
            acc[1][0] += a1 * b0; acc[1][1] += a1 * b1;
            acc[2][0] += a2 * b0; acc[2][1] += a2 * b1;
            acc[3][0] += a3 * b0; acc[3][1] += a3 * b1;
        }
    }

    // ---- epilogue ----------------------------------------------------------
    const float* W3 = W + 3 * H_;
    const int* mb = mask + bb * N_;

#pragma unroll
    for (int m = 0; m < 4; m++) {
        const int li = ig * 4 + m;
        const int i  = i0 + li;
        // repeat_interleave(dim=0).view quirk: one-hot row = (b*128+i)//8
        const int aidx = bb * 16 + (i >> 3);
        const float ri = rs[li];
        const bool mi = mb[i] != 0;

        float v[2];
#pragma unroll
        for (int n = 0; n < 2; n++) {
            const int j = j0 + jg * 2 + n;
            float vv = acc[m][n] + ri + rs[32 + jg * 2 + n] + W3[j + 127 - aidx];
            if (!(mi && (mb[j] != 0))) vv = -CUDART_INF_F;
            v[n] = vv;
        }
        *(float2*)(out + (bb * N_ + i) * N_ + j0 + jg * 2) = make_float2(v[0], v[1]);

        // partial argmax over this tile's 32 columns (first-occurrence ties)
        float best = v[0];
        int   bj   = j0 + jg * 2;
        if (v[1] > best) { best = v[1]; bj = j0 + jg * 2 + 1; }
#pragma unroll
        for (int off = 8; off; off >>= 1) {
            float ov = __shfl_down_sync(0xffffffffu, best, off, 16);
            int   oj = __shfl_down_sync(0xffffffffu, bj,   off, 16);
            if (ov > best || (ov == best && oj < bj)) { best = ov; bj = oj; }
        }
        if (jg == 0) {
            g_pval[(bb * N_ + i) * 4 + jt] = best;
            g_pidx[(bb * N_ + i) * 4 + jt] = bj;
        }
    }

    // ---- last-arriving block decodes preds --------------------------------
    __threadfence();                       // publish partials before counter
    __syncthreads();
    __shared__ int slast;
    if (t == 0) slast = atomicAdd(&g_cnt, 1);
    __syncthreads();
    if (slast == gridDim.x * gridDim.y * gridDim.z - 1) {
        for (int r = t; r < B_ * N_; r += 128) {
            float bv = g_pval[r * 4 + 0];
            int   bj = g_pidx[r * 4 + 0];
#pragma unroll
            for (int q = 1; q < 4; q++) {
                float v = g_pval[r * 4 + q];
                if (v > bv) { bv = v; bj = g_pidx[r * 4 + q]; }  // idx grows with q
            }
            preds[r] = (float)bj;
        }
        __syncthreads();
        if (t == 0) g_cnt = 0;   // reset for next graph replay
    }
}

// ---------------------------------------------------------------------------
extern "C" void kernel_launch(void* const* d_in, const int* in_sizes, int n_in,
                              void* d_out, int out_size) {
    const float* x    = (const float*)d_in[0];   // [8,128,256] float32
    const int*   mask = (const int*)d_in[1];     // [8,128] bool -> int32
    const float* W    = (const float*)d_in[2];   // [1,1023] float32
    const float* bias = (const float*)d_in[3];   // [1] float32
    float* out = (float*)d_out;

    const int nlog = B_ * N_ * N_;               // 131072
    float* preds = out + nlog;                   // [1024] as float

    dim3 grid(N_ / BN, N_ / BM, B_);             // (4,4,8) = 128 blocks
    pair_fused_kernel<<<grid, 128>>>(x, mask, W, bias, out, preds);
}

// round 5
// speedup vs baseline: 1.1248x; 1.1248x over previous
#include <cuda_runtime.h>
#include <math_constants.h>

// Problem constants (fixed by setup_inputs): B=8, N=128, H=256, F=1023
#define B_ 8
#define N_ 128
#define H_ 256

#define BM 32
#define BN 32
#define BK 64
#define STR 33    // k-major smem row stride: conflict-free scalar LDS

// Scratch: per-(row, j-tile) partial argmax + completion counter
__device__ float g_pval[B_ * N_ * 4];
__device__ int   g_pidx[B_ * N_ * 4];
__device__ int   g_cnt;          // zero-initialized; last block resets to 0

// ---------------------------------------------------------------------------
// Fused kernel, 256 threads: warps 0-3 (h=0) take k in [0,128),
// warps 4-7 (h=1) take k in [128,256). Each half runs the R2-style
// 32x32-tile GEMM on its k-range; halves reduce through smem; half 0
// does the epilogue (logits + mask + partial argmax); last block decodes.
// ---------------------------------------------------------------------------
__global__ void __launch_bounds__(256)
pair_fused_kernel(const float* __restrict__ x,
                  const int* __restrict__ mask,
                  const float* __restrict__ W,
                  const float* __restrict__ bias,
                  float* __restrict__ out,
                  float* __restrict__ preds) {
    __shared__ float As[2][BK][STR];
    __shared__ float Bs[2][BK][STR];
    __shared__ float rs[64];              // [0:32) r_i(+bias), [32:64) s_j
    __shared__ float red[128 * 9];        // half-1 partial accs (stride 9)

    const int t  = threadIdx.x;
    const int h  = t >> 7;                // k-half 0/1
    const int t2 = t & 127;
    const int jt = blockIdx.x, it = blockIdx.y, bb = blockIdx.z;
    const int i0 = it * BM, j0 = jt * BN;
    const float* xb = x + bb * N_ * H_;
    const float* W2 = W + 2 * H_;

    // ---- prologue: row dots (64 rows x 4 threads each, 64 floats/thread) --
    {
        const int pr = t >> 2;            // 0..63
        const int qt = t & 3;             // k-quarter
        const int grow = (pr < 32) ? (i0 + pr) : (j0 + (pr - 32));
        const float* xr = xb + grow * H_ + qt * 64;
        const float* wr = W + ((pr < 32) ? 0 : H_) + qt * 64;
        float sum = 0.f;
#pragma unroll
        for (int q = 0; q < 16; q++) {
            float4 xv = ((const float4*)xr)[q];
            float4 wv = ((const float4*)wr)[q];
            sum += xv.x * wv.x + xv.y * wv.y + xv.z * wv.z + xv.w * wv.w;
        }
        sum += __shfl_xor_sync(0xffffffffu, sum, 1);
        sum += __shfl_xor_sync(0xffffffffu, sum, 2);
        if (qt == 0) rs[pr] = sum + ((pr < 32) ? bias[0] : 0.f);
    }

    // ---- main GEMM: each half covers 128 k in two BK=64 passes ------------
    const int lr = t2 >> 4;   // loader row group 0..7
    const int lc = t2 & 15;   // loader k-quad 0..15
    const int ig = t2 >> 4;   // compute: 8 groups of 4 rows
    const int jg = t2 & 15;   // compute: 16 groups of 2 cols
    const int kbase = h * 128;

    float acc[4][2] = {};

    for (int k0 = 0; k0 < 128; k0 += BK) {
        __syncthreads();     // covers prologue on first iter, reads on later
        const int kg = kbase + k0;
        float4 wv = *(const float4*)(W2 + kg + lc * 4);
#pragma unroll
        for (int rep = 0; rep < 4; rep++) {
            int row = lr + rep * 8;
            float4 av = *(const float4*)(xb + (i0 + row) * H_ + kg + lc * 4);
            float4 bv = *(const float4*)(xb + (j0 + row) * H_ + kg + lc * 4);
            As[h][lc * 4 + 0][row] = av.x;
            As[h][lc * 4 + 1][row] = av.y;
            As[h][lc * 4 + 2][row] = av.z;
            As[h][lc * 4 + 3][row] = av.w;
            Bs[h][lc * 4 + 0][row] = bv.x * wv.x;
            Bs[h][lc * 4 + 1][row] = bv.y * wv.y;
            Bs[h][lc * 4 + 2][row] = bv.z * wv.z;
            Bs[h][lc * 4 + 3][row] = bv.w * wv.w;
        }
        __syncthreads();
#pragma unroll
        for (int k = 0; k < BK; k++) {
            float a0 = As[h][k][ig * 4 + 0];
            float a1 = As[h][k][ig * 4 + 1];
            float a2 = As[h][k][ig * 4 + 2];
            float a3 = As[h][k][ig * 4 + 3];
            float b0 = Bs[h][k][jg * 2 + 0];
            float b1 = Bs[h][k][jg * 2 + 1];
            acc[0][0] += a0 * b0; acc[0][1] += a0 * b1;
            acc[1][0] += a1 * b0; acc[1][1] += a1 * b1;
            acc[2][0] += a2 * b0; acc[2][1] += a2 * b1;
            acc[3][0] += a3 * b0; acc[3][1] += a3 * b1;
        }
    }

    // ---- combine k-halves --------------------------------------------------
    __syncthreads();
    if (h == 1) {
        float* dst = red + t2 * 9;        // stride 9: conflict-free
#pragma unroll
        for (int m = 0; m < 4; m++) {
            dst[m * 2 + 0] = acc[m][0];
            dst[m * 2 + 1] = acc[m][1];
        }
    }
    __syncthreads();

    // ---- epilogue (half 0 only) -------------------------------------------
    if (h == 0) {
        const float* src = red + t2 * 9;
        const float* W3 = W + 3 * H_;
        const int* mb = mask + bb * N_;

#pragma unroll
        for (int m = 0; m < 4; m++) {
            const int li = ig * 4 + m;
            const int i  = i0 + li;
            // repeat_interleave(dim=0).view quirk: one-hot row = (b*128+i)//8
            const int aidx = bb * 16 + (i >> 3);
            const float ri = rs[li];
            const bool mi = mb[i] != 0;

            float v[2];
#pragma unroll
            for (int n = 0; n < 2; n++) {
                const int j = j0 + jg * 2 + n;
                float vv = acc[m][n] + src[m * 2 + n] + ri
                         + rs[32 + jg * 2 + n] + W3[j + 127 - aidx];
                if (!(mi && (mb[j] != 0))) vv = -CUDART_INF_F;
                v[n] = vv;
            }
            *(float2*)(out + (bb * N_ + i) * N_ + j0 + jg * 2)
                = make_float2(v[0], v[1]);

            // partial argmax over this tile's 32 cols (first-occurrence ties)
            float best = v[0];
            int   bj   = j0 + jg * 2;
            if (v[1] > best) { best = v[1]; bj = j0 + jg * 2 + 1; }
#pragma unroll
            for (int off = 8; off; off >>= 1) {
                float ov = __shfl_down_sync(0xffffffffu, best, off, 16);
                int   oj = __shfl_down_sync(0xffffffffu, bj,   off, 16);
                if (ov > best || (ov == best && oj < bj)) { best = ov; bj = oj; }
            }
            if (jg == 0) {
                g_pval[(bb * N_ + i) * 4 + jt] = best;
                g_pidx[(bb * N_ + i) * 4 + jt] = bj;
            }
        }
    }

    // ---- last-arriving block decodes preds --------------------------------
    __threadfence();                       // publish partials before counter
    __syncthreads();
    __shared__ int slast;
    if (t == 0) slast = atomicAdd(&g_cnt, 1);
    __syncthreads();
    if (slast == gridDim.x * gridDim.y * gridDim.z - 1) {
        for (int r = t; r < B_ * N_; r += 256) {
            float bv = g_pval[r * 4 + 0];
            int   bj = g_pidx[r * 4 + 0];
#pragma unroll
            for (int q = 1; q < 4; q++) {
                float v = g_pval[r * 4 + q];
                if (v > bv) { bv = v; bj = g_pidx[r * 4 + q]; }  // idx grows with q
            }
            preds[r] = (float)bj;
        }
        __syncthreads();
        if (t == 0) g_cnt = 0;   // reset for next graph replay
    }
}

// ---------------------------------------------------------------------------
extern "C" void kernel_launch(void* const* d_in, const int* in_sizes, int n_in,
                              void* d_out, int out_size) {
    const float* x    = (const float*)d_in[0];   // [8,128,256] float32
    const int*   mask = (const int*)d_in[1];     // [8,128] bool -> int32
    const float* W    = (const float*)d_in[2];   // [1,1023] float32
    const float* bias = (const float*)d_in[3];   // [1] float32
    float* out = (float*)d_out;

    const int nlog = B_ * N_ * N_;               // 131072
    float* preds = out + nlog;                   // [1024] as float

    dim3 grid(N_ / BN, N_ / BM, B_);             // (4,4,8) = 128 blocks
    pair_fused_kernel<<<grid, 256>>>(x, mask, W, bias, out, preds);
}